// round 8
// baseline (speedup 1.0000x reference)
#include <cuda_runtime.h>
#include <cstdint>

// SKA: out[n, g*8+c, h, w] = sum_{7x7} x_pad[n, g*8+c, h+i, w+j] * w[n, c, i*7+j, h, w]
// x [8,512,96,96] f32, w [8,8,49,96,96] f32, out [8,512,96,96] f32.
//
// R8: vertical 2-pixel dataflow (thread owns output rows 2q, 2q+1 of one f32x2
// column pair): the two 7-row windows share 6 rows, so one 8-row sweep feeds 4
// outputs -> 64 B LDS per output (was 112). 2x49 weight pairs = 196 regs cached
// for all 64 g. Resource fix vs the failed R5 attempt: 96-thread CTAs with
// launch_bounds(96,3) -> 3 CTAs/SM (9 warps, 3 barrier domains), and a hard
// register diet everywhere else: scalar odd taps, zero-reg staging addressing
// (col = tid, row offsets are immediates, validity in one bitmask, cp.async
// ZFILL src_size=0 for OOB rows). 4-buffer depth-3 cp.async pipeline.

#define N_    8
#define IC    512
#define H_    96
#define W_    96
#define WC    8
#define G_    64
#define KS    7
#define PAD   3
#define HT    4                     // output rows per CTA (2 row-groups x 2)
#define PAIRS 48
#define NTHR  96                    // 2 row-groups x 48 pairs; == W_ (staging!)
#define TROWS (HT + 2 * PAD)        // 10 staged rows
#define PITCH 104                   // 3 zero | 96 data | 5 zero (floats)
#define TILE_F (TROWS * PITCH)      // 1040 floats per channel slab
#define HW    (H_ * W_)             // 9216
#define CSTR  ((size_t)WC * HW)     // x/out channel stride between g steps
#define NIT   (G_ / 2)              // 32 pipeline stages (2 channels each)

typedef unsigned long long u64;

static __device__ __forceinline__ void ffma2(u64& d, u64 a, u64 b) {
    asm("fma.rn.f32x2 %0, %1, %2, %0;" : "+l"(d) : "l"(a), "l"(b));
}
// lo += xl*w.lo, hi += xh*w.hi; splitting the weight pair is register aliasing.
static __device__ __forceinline__ void odd_tap(float& lo, float& hi,
                                               float xl, float xh, u64 w) {
    asm("{\n\t"
        ".reg .f32 wl, wh;\n\t"
        "mov.b64 {wl, wh}, %4;\n\t"
        "fma.rn.f32 %0, %2, wl, %0;\n\t"
        "fma.rn.f32 %1, %3, wh, %1;\n\t"
        "}" : "+f"(lo), "+f"(hi) : "f"(xl), "f"(xh), "l"(w));
}
static __device__ __forceinline__ void unpack2(u64 v, float& a, float& b) {
    asm("mov.b64 {%0, %1}, %2;" : "=f"(a), "=f"(b) : "l"(v));
}
static __device__ __forceinline__ u64 pack2(float a, float b) {
    u64 r; asm("mov.b64 %0, {%1, %2};" : "=l"(r) : "f"(a), "f"(b)); return r;
}
// cp.async ZFILL idiom: sz==0 reads nothing (address unused), writes 4 zero bytes.
static __device__ __forceinline__ void cp4(uint32_t s, const float* g, int sz) {
    asm volatile("cp.async.ca.shared.global [%0], [%1], 4, %2;"
                 :: "r"(s), "l"(g), "r"(sz));
}

__global__ __launch_bounds__(NTHR, 3)
void ska_kernel(const float* __restrict__ x, const float* __restrict__ wgt,
                float* __restrict__ out) {
    __shared__ float smem[8 * TILE_F];   // 4 buffers x 2 channel slabs = 33.3 KB

    const int tid = threadIdx.x;
    const int ht  = blockIdx.x;          // 0..23
    const int c   = blockIdx.y;          // 0..7
    const int n   = blockIdx.z;          // 0..7
    const int h0  = ht * HT;
    const int q   = tid / PAIRS;         // 0..1 -> output rows 2q, 2q+1
    const int p   = tid % PAIRS;
    const int r0  = 2 * q;
    const int w0  = 2 * p;

    // Zero left/right halo columns of all 8 slabs (written once, never again).
    for (int z = tid; z < 8 * TROWS * 8; z += NTHR) {
        int b = z / (TROWS * 8), rem = z % (TROWS * 8);
        int row = rem / 8, ci = rem % 8;
        int col = (ci < 3) ? ci : 99 + (ci - 3);
        smem[b * TILE_F + row * PITCH + col] = 0.0f;
    }

    // Register-cache both pixels' 49 weight pairs (reused for all 64 g).
    const float* wb = wgt + ((size_t)(n * WC + c) * 49) * HW
                          + (size_t)(h0 + r0) * W_ + w0;
    u64 W0[49], W1[49];
    #pragma unroll
    for (int t = 0; t < 49; t++) {
        W0[t] = *(const u64*)(wb + (size_t)t * HW);
        W1[t] = *(const u64*)(wb + (size_t)t * HW + W_);
    }

    // Staging: thread stages column `tid` of each of the 10 tile rows.
    // Row k's gmem row is h0-3+k; OOB rows are ZFILLed (address never read).
    const float* xc = x + (size_t)n * IC * HW + (size_t)c * HW;
    const float* gx = xc + (long)(h0 - PAD) * W_ + tid;   // may point OOB; ok
    unsigned vmask = 0;                                   // 3 bits per row: 4|0
    #pragma unroll
    for (int k = 0; k < TROWS; k++) {
        int hr = h0 - PAD + k;
        if (hr >= 0 && hr < H_) vmask |= 4u << (3 * k);
    }
    const uint32_t sbase = (uint32_t)__cvta_generic_to_shared(smem)
                         + (uint32_t)(3 + tid) * 4u;

    // Stage channels (2s, 2s+1) into buffer s%4; commit one cp.async group.
    auto stage = [&](int s) {
        #pragma unroll
        for (int cc = 0; cc < 2; cc++) {
            uint32_t sb = sbase + (uint32_t)(((s & 3) * 2 + cc) * TILE_F) * 4u;
            const float* bp = gx + (size_t)cc * CSTR;
            #pragma unroll
            for (int k = 0; k < TROWS; k++)
                cp4(sb + (uint32_t)(k * PITCH) * 4u, bp + k * W_,
                    (int)((vmask >> (3 * k)) & 7u));
        }
        asm volatile("cp.async.commit_group;");
        gx += 2 * CSTR;
    };

    stage(0);
    stage(1);
    stage(2);

    float* op = out + (size_t)n * IC * HW + (size_t)c * HW
                    + (size_t)(h0 + r0) * W_ + w0;

    for (int it = 0; it < NIT; ++it) {
        // Drain group `it` in this thread, then barrier makes all threads'
        // group-`it` smem writes visible. Tail: fewer groups remain pending.
        if (it == NIT - 1)      { asm volatile("cp.async.wait_group 0;"); }
        else if (it == NIT - 2) { asm volatile("cp.async.wait_group 1;"); }
        else                    { asm volatile("cp.async.wait_group 2;"); }
        __syncthreads();
        // Stage buffer (it+3)%4 = (it-1)%4: the barrier just proved everyone
        // finished compute on iteration it-1. Compute below reads (it)%4.
        if (it + 3 < NIT) stage(it + 3);

        const float* tbB = smem + (it & 3) * 2 * TILE_F;
        #pragma unroll
        for (int gg = 0; gg < 2; gg++) {
            const float* tbp = tbB + gg * TILE_F + r0 * PITCH + w0;
            u64 aE0 = 0ull, aE1 = 0ull;            // packed even-tap chains
            float s0l = 0.f, s0h = 0.f, s1l = 0.f, s1h = 0.f;  // scalar odd
            #pragma unroll
            for (int k = 0; k < 8; k++) {          // tile rows r0+k feed both px
                const u64* rp = (const u64*)(tbp + k * PITCH);  // 8B aligned
                u64 U0 = rp[0], U1 = rp[1], U2 = rp[2], U3 = rp[3];
                float f0, f1, f2, f3, f4, f5, f6, f7;
                unpack2(U0, f0, f1); unpack2(U1, f2, f3);
                unpack2(U2, f4, f5); unpack2(U3, f6, f7);
                if (k < 7) {                       // pixel0, kernel row i = k
                    ffma2(aE0, U0, W0[k * 7 + 0]);
                    ffma2(aE0, U1, W0[k * 7 + 2]);
                    ffma2(aE0, U2, W0[k * 7 + 4]);
                    ffma2(aE0, U3, W0[k * 7 + 6]);
                    odd_tap(s0l, s0h, f1, f2, W0[k * 7 + 1]);
                    odd_tap(s0l, s0h, f3, f4, W0[k * 7 + 3]);
                    odd_tap(s0l, s0h, f5, f6, W0[k * 7 + 5]);
                }
                if (k >= 1) {                      // pixel1, kernel row i = k-1
                    const int i = k - 1;
                    ffma2(aE1, U0, W1[i * 7 + 0]);
                    ffma2(aE1, U1, W1[i * 7 + 2]);
                    ffma2(aE1, U2, W1[i * 7 + 4]);
                    ffma2(aE1, U3, W1[i * 7 + 6]);
                    odd_tap(s1l, s1h, f1, f2, W1[i * 7 + 1]);
                    odd_tap(s1l, s1h, f3, f4, W1[i * 7 + 3]);
                    odd_tap(s1l, s1h, f5, f6, W1[i * 7 + 5]);
                }
            }
            float e0, e1, g0, g1;
            unpack2(aE0, e0, e1);
            unpack2(aE1, g0, g1);
            *(u64*)op        = pack2(e0 + s0l, e1 + s0h);
            *(u64*)(op + W_) = pack2(g0 + s1l, g1 + s1h);
            op += CSTR;
        }
    }
}

extern "C" void kernel_launch(void* const* d_in, const int* in_sizes, int n_in,
                              void* d_out, int out_size) {
    const float* x = (const float*)d_in[0];
    const float* w = (const float*)d_in[1];
    // x (37,748,736 elems) > w (28,901,376); guard against input ordering.
    if (n_in >= 2 && in_sizes[0] < in_sizes[1]) {
        const float* t = x; x = w; w = t;
    }
    float* out = (float*)d_out;
    dim3 grid(H_ / HT, WC, N_);   // (24, 8, 8) = 1536 CTAs, 3 per SM
    ska_kernel<<<grid, NTHR>>>(x, w, out);
}

// round 9
// speedup vs baseline: 2.4047x; 2.4047x over previous
#include <cuda_runtime.h>
#include <cstdint>

// SKA: out[n, g*8+c, h, w] = sum_{7x7} x_pad[n, g*8+c, h+i, w+j] * w[n, c, i*7+j, h, w]
// x [8,512,96,96] f32, w [8,8,49,96,96] f32, out [8,512,96,96] f32.
//
// R9: cooperative lane-pair quad. Lanes (2t, 2t+1) = roles (A, B) jointly own a
// 2x2 output quad (rows 2rg,2rg+1 x one f32x2 col pair). The 8-row x sweep is
// split by tile row: A reads rows 0..3 of the window, B rows 7..4 (reverse).
// Tap work splits exactly 49/49: A = px0 i0-3 + px1 i0-2, B = px0 i4-6 +
// px1 i3-6. Each thread holds 49 weight pairs (98 regs, the proven resource
// point) but LDS falls to 128 B/thread/g = 64 B/output (was 112). Each role's
// single 7-tap "light" row belongs to the pixel it stores -> uniform control
// flow; partials merge with one shfl.bfly(1) + fadd2. PITCH=112 == 16 (mod 32
// words) puts A/B rows (odd row distance) on disjoint bank halves.
// Rest = R6 winner: 192 thr, HT=4, 2 CTAs/SM, 4-buf depth-3 cp.async pipeline.

#define N_    8
#define IC    512
#define H_    96
#define W_    96
#define WC    8
#define G_    64
#define PAD   3
#define HT    4                     // output rows per CTA (2 row-groups x 2)
#define NTHR  192
#define TROWS (HT + 2 * PAD)        // 10 staged rows
#define PITCH 112                   // 3 zero | 96 data | zeros...; 112%32==16
#define TILE_F (TROWS * PITCH)      // 1120 floats per channel slab
#define HW    (H_ * W_)             // 9216
#define CSTR  ((size_t)WC * HW)     // x/out channel stride between g steps
#define NIT   (G_ / 2)              // 32 pipeline stages (2 channels each)
#define ELPT  ((TROWS * W_) / NTHR) // 5 staged elements per thread per channel

typedef unsigned long long u64;

static __device__ __forceinline__ void ffma2(u64& d, u64 a, u64 b) {
    asm("fma.rn.f32x2 %0, %1, %2, %0;" : "+l"(d) : "l"(a), "l"(b));
}
static __device__ __forceinline__ u64 fadd2(u64 a, u64 b) {
    u64 d; asm("add.rn.f32x2 %0, %1, %2;" : "=l"(d) : "l"(a), "l"(b)); return d;
}
// lo += xl*w.lo, hi += xh*w.hi; splitting the weight pair is register aliasing.
static __device__ __forceinline__ void odd_tap(float& lo, float& hi,
                                               float xl, float xh, u64 w) {
    asm("{\n\t"
        ".reg .f32 wl, wh;\n\t"
        "mov.b64 {wl, wh}, %4;\n\t"
        "fma.rn.f32 %0, %2, wl, %0;\n\t"
        "fma.rn.f32 %1, %3, wh, %1;\n\t"
        "}" : "+f"(lo), "+f"(hi) : "f"(xl), "f"(xh), "l"(w));
}
static __device__ __forceinline__ void unpack2(u64 v, float& a, float& b) {
    asm("mov.b64 {%0, %1}, %2;" : "=f"(a), "=f"(b) : "l"(v));
}
static __device__ __forceinline__ u64 pack2(float a, float b) {
    u64 r; asm("mov.b64 %0, {%1, %2};" : "=l"(r) : "f"(a), "f"(b)); return r;
}
static __device__ __forceinline__ u64 shfl_x1(u64 v) {
    uint32_t lo = (uint32_t)v, hi = (uint32_t)(v >> 32);
    lo = __shfl_xor_sync(0xffffffffu, lo, 1);
    hi = __shfl_xor_sync(0xffffffffu, hi, 1);
    return ((u64)hi << 32) | lo;
}
static __device__ __forceinline__ void cp4(uint32_t s, const float* g, int sz) {
    asm volatile("cp.async.ca.shared.global [%0], [%1], 4, %2;"
                 :: "r"(s), "l"(g), "r"(sz));
}

// 7 taps of one kernel row into one chain set (even pairs + odd scalars).
#define TAP7(E, LO, HI, WA)                          \
    do {                                             \
        ffma2(E, U0, (WA)[0]);                       \
        ffma2(E, U1, (WA)[2]);                       \
        ffma2(E, U2, (WA)[4]);                       \
        ffma2(E, U3, (WA)[6]);                       \
        odd_tap(LO, HI, f1, f2, (WA)[1]);            \
        odd_tap(LO, HI, f3, f4, (WA)[3]);            \
        odd_tap(LO, HI, f5, f6, (WA)[5]);            \
    } while (0)

__global__ __launch_bounds__(NTHR, 2)
void ska_kernel(const float* __restrict__ x, const float* __restrict__ wgt,
                float* __restrict__ out) {
    __shared__ float smem[8 * TILE_F];   // 4 buffers x 2 channel slabs = 35 KB

    const int tid  = threadIdx.x;
    const int ht   = blockIdx.x;         // 0..23
    const int c    = blockIdx.y;         // 0..7
    const int n    = blockIdx.z;         // 0..7
    const int h0   = ht * HT;
    const int role = tid & 1;            // 0 = A (rows 0..3), 1 = B (rows 7..4)
    const int pid  = tid >> 1;           // 0..95
    const int rg   = pid / 48;           // row-group: output rows 2rg, 2rg+1
    const int cp   = pid % 48;
    const int w0   = 2 * cp;

    // Zero left/right halo columns of all 8 slabs (reads touch floats 0..101).
    for (int z = tid; z < 8 * TROWS * 8; z += NTHR) {
        int b = z / (TROWS * 8), rem = z % (TROWS * 8);
        int row = rem / 8, ci = rem % 8;
        int col = (ci < 3) ? ci : 99 + (ci - 3);
        smem[b * TILE_F + row * PITCH + col] = 0.0f;
    }

    // Weight register cache: exactly 49 pairs per thread (98 regs).
    // own  = the pixel this role stores (A: row 2rg; B: row 2rg+1).
    // A: light = own i=0;  heavy m=0..2: own i=m+1, other i=m.
    // B: light = own i=6;  heavy m=0..2: own i=5-m, other i=6-m.
    const float* W0b = wgt + ((size_t)(n * WC + c) * 49) * HW
                           + (size_t)(h0 + 2 * rg) * W_ + w0;
    const float* ownB = role ? (W0b + W_) : W0b;
    const float* othB = role ? W0b : (W0b + W_);
    u64 WL[7], WHo[3][7], WHx[3][7];
    {
        const int liRow = role ? 6 : 0;
        #pragma unroll
        for (int j = 0; j < 7; j++)
            WL[j] = *(const u64*)(ownB + (size_t)(liRow * 7 + j) * HW);
        #pragma unroll
        for (int m = 0; m < 3; m++) {
            const int ro = role ? (5 - m) : (m + 1);
            const int rx = role ? (6 - m) : m;
            #pragma unroll
            for (int j = 0; j < 7; j++) {
                WHo[m][j] = *(const u64*)(ownB + (size_t)(ro * 7 + j) * HW);
                WHx[m][j] = *(const u64*)(othB + (size_t)(rx * 7 + j) * HW);
            }
        }
    }

    // Staging (same scheme as R6): 10 rows x 96 cols, col = f(tid), ELPT=5.
    const float* xc = x + (size_t)n * IC * HW + (size_t)c * HW;  // g=0 channel
    const uint32_t sbase = (uint32_t)__cvta_generic_to_shared(smem);
    uint32_t soff[ELPT];
    int      gofs[ELPT];
    int      gsz[ELPT];
    #pragma unroll
    for (int k = 0; k < ELPT; k++) {
        int idx = tid + k * NTHR;            // 0..959
        int row = idx / W_, col = idx - row * W_;
        int hr  = h0 - PAD + row;
        gsz[k]  = (hr >= 0 && hr < H_) ? 4 : 0;
        int hrc = hr < 0 ? 0 : (hr >= H_ ? H_ - 1 : hr);
        soff[k] = (uint32_t)(row * PITCH + 3 + col) * 4u;
        gofs[k] = hrc * W_ + col;
    }
    const float* gx = xc;
    auto stage = [&](int s) {
        #pragma unroll
        for (int cc = 0; cc < 2; cc++) {
            uint32_t sb = sbase + (uint32_t)(((s & 3) * 2 + cc) * TILE_F) * 4u;
            const float* base = gx + (size_t)cc * CSTR;
            #pragma unroll
            for (int k = 0; k < ELPT; k++)
                cp4(sb + soff[k], base + gofs[k], gsz[k]);
        }
        asm volatile("cp.async.commit_group;");
        gx += 2 * CSTR;
    };

    stage(0);
    stage(1);
    stage(2);

    // Per-thread tile-row float offsets: A row kk, B row 7-kk (plus row-group).
    int rowF[4];
    #pragma unroll
    for (int kk = 0; kk < 4; kk++)
        rowF[kk] = (2 * rg + (role ? (7 - kk) : kk)) * PITCH + w0;

    float* op = out + (size_t)n * IC * HW + (size_t)c * HW
                    + (size_t)(h0 + 2 * rg + role) * W_ + w0;

    for (int it = 0; it < NIT; ++it) {
        // Drain group `it` in this thread; barrier publishes all smem writes.
        if (it == NIT - 1)      { asm volatile("cp.async.wait_group 0;"); }
        else if (it == NIT - 2) { asm volatile("cp.async.wait_group 1;"); }
        else                    { asm volatile("cp.async.wait_group 2;"); }
        __syncthreads();
        // Stage buffer (it+3)%4 = (it-1)%4: barrier proved iter it-1 finished.
        if (it + 3 < NIT) stage(it + 3);

        const float* tbB = smem + (it & 3) * 2 * TILE_F;
        #pragma unroll
        for (int gg = 0; gg < 2; gg++) {
            const float* tb = tbB + gg * TILE_F;
            u64 eO = 0ull, eX = 0ull;               // even-tap chains
            float oLo = 0.f, oHi = 0.f, xLo = 0.f, xHi = 0.f;  // odd scalars
            // Light row (kk=0): 7 taps into the own-pixel chains.
            {
                const u64* rp = (const u64*)(tb + rowF[0]);  // 8B aligned
                u64 U0 = rp[0], U1 = rp[1], U2 = rp[2], U3 = rp[3];
                float f0, f1, f2, f3, f4, f5, f6, f7;
                unpack2(U0, f0, f1); unpack2(U1, f2, f3);
                unpack2(U2, f4, f5); unpack2(U3, f6, f7);
                TAP7(eO, oLo, oHi, WL);
            }
            // Heavy rows (kk=1..3): 7 taps own + 7 taps other.
            #pragma unroll
            for (int kk = 1; kk < 4; kk++) {
                const u64* rp = (const u64*)(tb + rowF[kk]);
                u64 U0 = rp[0], U1 = rp[1], U2 = rp[2], U3 = rp[3];
                float f0, f1, f2, f3, f4, f5, f6, f7;
                unpack2(U0, f0, f1); unpack2(U1, f2, f3);
                unpack2(U2, f4, f5); unpack2(U3, f6, f7);
                TAP7(eO, oLo, oHi, WHo[kk - 1]);
                TAP7(eX, xLo, xHi, WHx[kk - 1]);
            }
            // Fold, swap the other-pixel partial with the partner lane, store.
            u64 ownF = fadd2(eO, pack2(oLo, oHi));
            u64 othF = fadd2(eX, pack2(xLo, xHi));
            u64 recv = shfl_x1(othF);   // partner's partial for MY pixel
            *(u64*)op = fadd2(ownF, recv);
            op += CSTR;
        }
    }
}

extern "C" void kernel_launch(void* const* d_in, const int* in_sizes, int n_in,
                              void* d_out, int out_size) {
    const float* x = (const float*)d_in[0];
    const float* w = (const float*)d_in[1];
    // x (37,748,736 elems) > w (28,901,376); guard against input ordering.
    if (n_in >= 2 && in_sizes[0] < in_sizes[1]) {
        const float* t = x; x = w; w = t;
    }
    float* out = (float*)d_out;
    dim3 grid(H_ / HT, WC, N_);   // (24, 8, 8) = 1536 CTAs, 2 per SM
    ska_kernel<<<grid, NTHR>>>(x, w, out);
}